// round 1
// baseline (speedup 1.0000x reference)
#include <cuda_runtime.h>

#define B_   8
#define S_   2048
#define NEXP 16
#define DIN_ 1024
#define DOUT_ 1024

// Scratch (no cudaMalloc allowed): mixed weights + mixed bias
__device__ float g_Wm[B_ * DOUT_ * DIN_];   // [B, DOUT, DIN]
__device__ float g_mb[B_ * DOUT_];          // [B, DOUT]

// -------------------- packed f32x2 FMA --------------------
__device__ __forceinline__ float2 ffma2(float2 a, float2 b, float2 c) {
    unsigned long long ua, ub, uc, ud;
    ua = *reinterpret_cast<unsigned long long*>(&a);
    ub = *reinterpret_cast<unsigned long long*>(&b);
    uc = *reinterpret_cast<unsigned long long*>(&c);
    asm("fma.rn.f32x2 %0, %1, %2, %3;" : "=l"(ud) : "l"(ua), "l"(ub), "l"(uc));
    return *reinterpret_cast<float2*>(&ud);
}

// -------------------- Kernel 1: mix weights --------------------
// Each thread owns one float4 position of [DOUT*DIN], accumulates all 8 batches.
// W read exactly once from DRAM.
__global__ void mix_w_kernel(const float* __restrict__ p, const float* __restrict__ W) {
    __shared__ float sp[B_ * NEXP];
    if (threadIdx.x < B_ * NEXP) sp[threadIdx.x] = p[threadIdx.x];
    __syncthreads();

    int idx = blockIdx.x * blockDim.x + threadIdx.x;   // float4 index
    const int stride4 = DOUT_ * DIN_ / 4;
    if (idx >= stride4) return;

    const float4* W4  = reinterpret_cast<const float4*>(W);
    float4*       Wm4 = reinterpret_cast<float4*>(g_Wm);

    float4 acc[B_];
#pragma unroll
    for (int b = 0; b < B_; b++) acc[b] = make_float4(0.f, 0.f, 0.f, 0.f);

#pragma unroll
    for (int n = 0; n < NEXP; n++) {
        float4 w = W4[n * stride4 + idx];
#pragma unroll
        for (int b = 0; b < B_; b++) {
            float s = sp[b * NEXP + n];
            acc[b].x += s * w.x;
            acc[b].y += s * w.y;
            acc[b].z += s * w.z;
            acc[b].w += s * w.w;
        }
    }
#pragma unroll
    for (int b = 0; b < B_; b++) Wm4[b * stride4 + idx] = acc[b];
}

// -------------------- Kernel 1b: mix bias --------------------
__global__ void mix_b_kernel(const float* __restrict__ p, const float* __restrict__ bias) {
    int idx = blockIdx.x * blockDim.x + threadIdx.x;
    if (idx >= B_ * DOUT_) return;
    int b = idx >> 10;        // /1024
    int i = idx & 1023;
    float s = 0.f;
#pragma unroll
    for (int n = 0; n < NEXP; n++) s += p[b * NEXP + n] * bias[n * DOUT_ + i];
    g_mb[idx] = s;
}

// -------------------- Kernel 2: batched SGEMM (TN) + bias --------------------
// C[b][m][n] = sum_k X[b][m][k] * Wm[b][n][k] + mb[b][n]
#define BM 128
#define BN 128
#define BK 16
#define LDT 132   // BM + 4 padding (floats); 132*4B = 528B, 16B-aligned rows

__global__ __launch_bounds__(256) void gemm_kernel(const float* __restrict__ X,
                                                   float* __restrict__ Out) {
    __shared__ float As[2][BK][LDT];
    __shared__ float Bs[2][BK][LDT];

    const int b  = blockIdx.z;
    const int m0 = blockIdx.y * BM;
    const int n0 = blockIdx.x * BN;
    const int tid = threadIdx.x;

    const float* Aptr = X    + (size_t)b * S_ * DIN_;
    const float* Bptr = g_Wm + (size_t)b * DOUT_ * DIN_;

    // global->reg staging indices (each thread: 2 float4 for A, 2 for B)
    const int lrow0 = tid >> 2;   // 0..63
    const int lc4   = tid & 3;    // 0..3  (which float4 in the 16-wide k slab)

    float4 ra[2], rb[2];

    const int tx = tid & 15;      // n-dir
    const int ty = tid >> 4;      // m-dir

    float2 acc[8][4];
#pragma unroll
    for (int i = 0; i < 8; i++)
#pragma unroll
        for (int j = 0; j < 4; j++) acc[i][j] = make_float2(0.f, 0.f);

    // ---- prologue: load tile 0 ----
#pragma unroll
    for (int i = 0; i < 2; i++) {
        int row = lrow0 + i * 64;
        ra[i] = *reinterpret_cast<const float4*>(Aptr + (size_t)(m0 + row) * DIN_ + lc4 * 4);
        rb[i] = *reinterpret_cast<const float4*>(Bptr + (size_t)(n0 + row) * DIN_ + lc4 * 4);
    }
#pragma unroll
    for (int i = 0; i < 2; i++) {
        int row = lrow0 + i * 64;
        int kb  = lc4 * 4;
        As[0][kb + 0][row] = ra[i].x; As[0][kb + 1][row] = ra[i].y;
        As[0][kb + 2][row] = ra[i].z; As[0][kb + 3][row] = ra[i].w;
        Bs[0][kb + 0][row] = rb[i].x; Bs[0][kb + 1][row] = rb[i].y;
        Bs[0][kb + 2][row] = rb[i].z; Bs[0][kb + 3][row] = rb[i].w;
    }
    __syncthreads();

    const int NT = DIN_ / BK;   // 64
    for (int t = 0; t < NT; t++) {
        const int cur = t & 1;

        if (t + 1 < NT) {
            int k0 = (t + 1) * BK;
#pragma unroll
            for (int i = 0; i < 2; i++) {
                int row = lrow0 + i * 64;
                ra[i] = *reinterpret_cast<const float4*>(Aptr + (size_t)(m0 + row) * DIN_ + k0 + lc4 * 4);
                rb[i] = *reinterpret_cast<const float4*>(Bptr + (size_t)(n0 + row) * DIN_ + k0 + lc4 * 4);
            }
        }

#pragma unroll
        for (int kk = 0; kk < BK; kk++) {
            float4 a0 = *reinterpret_cast<const float4*>(&As[cur][kk][ty * 8]);
            float4 a1 = *reinterpret_cast<const float4*>(&As[cur][kk][ty * 8 + 4]);
            float4 b0 = *reinterpret_cast<const float4*>(&Bs[cur][kk][tx * 8]);
            float4 b1 = *reinterpret_cast<const float4*>(&Bs[cur][kk][tx * 8 + 4]);

            float av[8] = {a0.x, a0.y, a0.z, a0.w, a1.x, a1.y, a1.z, a1.w};
            float2 bv[4];
            bv[0] = make_float2(b0.x, b0.y);
            bv[1] = make_float2(b0.z, b0.w);
            bv[2] = make_float2(b1.x, b1.y);
            bv[3] = make_float2(b1.z, b1.w);

#pragma unroll
            for (int i = 0; i < 8; i++) {
                float2 aa = make_float2(av[i], av[i]);
#pragma unroll
                for (int j = 0; j < 4; j++) acc[i][j] = ffma2(aa, bv[j], acc[i][j]);
            }
        }

        if (t + 1 < NT) {
            const int nxt = (t + 1) & 1;
#pragma unroll
            for (int i = 0; i < 2; i++) {
                int row = lrow0 + i * 64;
                int kb  = lc4 * 4;
                As[nxt][kb + 0][row] = ra[i].x; As[nxt][kb + 1][row] = ra[i].y;
                As[nxt][kb + 2][row] = ra[i].z; As[nxt][kb + 3][row] = ra[i].w;
                Bs[nxt][kb + 0][row] = rb[i].x; Bs[nxt][kb + 1][row] = rb[i].y;
                Bs[nxt][kb + 2][row] = rb[i].z; Bs[nxt][kb + 3][row] = rb[i].w;
            }
            __syncthreads();
        }
    }

    // ---- epilogue: + mixed bias, write out ----
    float2 bias2[4];
#pragma unroll
    for (int j = 0; j < 4; j++) {
        bias2[j].x = g_mb[b * DOUT_ + n0 + tx * 8 + 2 * j + 0];
        bias2[j].y = g_mb[b * DOUT_ + n0 + tx * 8 + 2 * j + 1];
    }

#pragma unroll
    for (int i = 0; i < 8; i++) {
        int row = m0 + ty * 8 + i;
        float* o = Out + (size_t)b * S_ * DOUT_ + (size_t)row * DOUT_ + n0 + tx * 8;
        float4 v0, v1;
        v0.x = acc[i][0].x + bias2[0].x;
        v0.y = acc[i][0].y + bias2[0].y;
        v0.z = acc[i][1].x + bias2[1].x;
        v0.w = acc[i][1].y + bias2[1].y;
        v1.x = acc[i][2].x + bias2[2].x;
        v1.y = acc[i][2].y + bias2[2].y;
        v1.z = acc[i][3].x + bias2[3].x;
        v1.w = acc[i][3].y + bias2[3].y;
        *reinterpret_cast<float4*>(o)     = v0;
        *reinterpret_cast<float4*>(o + 4) = v1;
    }
}

// -------------------- launch --------------------
extern "C" void kernel_launch(void* const* d_in, const int* in_sizes, int n_in,
                              void* d_out, int out_size) {
    const float* x    = (const float*)d_in[0];   // [B, S, DIN]
    const float* p    = (const float*)d_in[1];   // [B, N]
    const float* W    = (const float*)d_in[2];   // [N, DOUT, DIN]
    const float* bias = (const float*)d_in[3];   // [N, DOUT]
    float* out = (float*)d_out;                  // [B, S, DOUT]

    {
        int total4 = DOUT_ * DIN_ / 4;           // 262144
        int threads = 256;
        int blocks = (total4 + threads - 1) / threads;
        mix_w_kernel<<<blocks, threads>>>(p, W);
    }
    {
        int total = B_ * DOUT_;
        int threads = 256;
        int blocks = (total + threads - 1) / threads;
        mix_b_kernel<<<blocks, threads>>>(p, bias);
    }
    {
        dim3 grid(DOUT_ / BN, S_ / BM, B_);      // (8, 16, 8)
        gemm_kernel<<<grid, 256>>>(x, out);
    }
}

// round 3
// speedup vs baseline: 3.1620x; 3.1620x over previous
#include <cuda_runtime.h>
#include <cuda_bf16.h>
#include <cstdint>

#define B_    8
#define S_    2048
#define NEXP  16
#define DIN_  1024
#define DOUT_ 1024

// ---------------- scratch (__device__ globals; no cudaMalloc allowed) ----------------
__device__ __align__(1024) __nv_bfloat16 g_Xhi[B_ * S_ * DIN_];
__device__ __align__(1024) __nv_bfloat16 g_Xlo[B_ * S_ * DIN_];
__device__ __align__(1024) __nv_bfloat16 g_Whi[B_ * DOUT_ * DIN_];
__device__ __align__(1024) __nv_bfloat16 g_Wlo[B_ * DOUT_ * DIN_];
__device__ float g_mb[B_ * DOUT_];

// ---------------- PTX helpers (all target-generic, sm_80+) ----------------
__device__ __forceinline__ uint32_t smem_u32(const void* p) {
    uint32_t a;
    asm("{ .reg .u64 t; cvta.to.shared.u64 t, %1; cvt.u32.u64 %0, t; }" : "=r"(a) : "l"(p));
    return a;
}
__device__ __forceinline__ void cpa16(uint32_t s, const void* g) {
    asm volatile("cp.async.cg.shared.global [%0], [%1], 16;" :: "r"(s), "l"(g));
}
__device__ __forceinline__ void cpa_commit() { asm volatile("cp.async.commit_group;" ::: "memory"); }
__device__ __forceinline__ void cpa_wait1()  { asm volatile("cp.async.wait_group 1;" ::: "memory"); }
__device__ __forceinline__ void cpa_wait0()  { asm volatile("cp.async.wait_group 0;" ::: "memory"); }

__device__ __forceinline__ void ldsm_x4(uint32_t (&r)[4], uint32_t addr) {
    asm volatile("ldmatrix.sync.aligned.m8n8.x4.shared.b16 {%0,%1,%2,%3}, [%4];"
                 : "=r"(r[0]), "=r"(r[1]), "=r"(r[2]), "=r"(r[3]) : "r"(addr));
}
__device__ __forceinline__ void mma16816(float (&d)[4], const uint32_t (&a)[4],
                                         uint32_t b0, uint32_t b1) {
    asm volatile(
        "mma.sync.aligned.m16n8k16.row.col.f32.bf16.bf16.f32 "
        "{%0,%1,%2,%3}, {%4,%5,%6,%7}, {%8,%9}, {%0,%1,%2,%3};"
        : "+f"(d[0]), "+f"(d[1]), "+f"(d[2]), "+f"(d[3])
        : "r"(a[0]), "r"(a[1]), "r"(a[2]), "r"(a[3]), "r"(b0), "r"(b1));
}

static __device__ __forceinline__ uint32_t swz(uint32_t off) {
    return off ^ ((off >> 3) & 0x70);
}

// ---------------- Kernel: X -> hi/lo bf16 ----------------
__global__ void conv_x_kernel(const float* __restrict__ X) {
    int idx = blockIdx.x * blockDim.x + threadIdx.x;
    const int total4 = B_ * S_ * DIN_ / 4;
    if (idx >= total4) return;
    float4 v = reinterpret_cast<const float4*>(X)[idx];
    union { __nv_bfloat16 h[4]; uint2 u; } hi, lo;
    float f[4] = {v.x, v.y, v.z, v.w};
#pragma unroll
    for (int i = 0; i < 4; i++) {
        __nv_bfloat16 h = __float2bfloat16(f[i]);
        hi.h[i] = h;
        lo.h[i] = __float2bfloat16(f[i] - __bfloat162float(h));
    }
    reinterpret_cast<uint2*>(g_Xhi)[idx] = hi.u;
    reinterpret_cast<uint2*>(g_Xlo)[idx] = lo.u;
}

// ---------------- Kernel: mix weights -> hi/lo bf16 ----------------
__global__ void mix_w_kernel(const float* __restrict__ p, const float* __restrict__ W) {
    __shared__ float sp[B_ * NEXP];
    if (threadIdx.x < B_ * NEXP) sp[threadIdx.x] = p[threadIdx.x];
    __syncthreads();

    int idx = blockIdx.x * blockDim.x + threadIdx.x;
    const int stride4 = DOUT_ * DIN_ / 4;
    if (idx >= stride4) return;

    const float4* W4 = reinterpret_cast<const float4*>(W);
    float4 acc[B_];
#pragma unroll
    for (int b = 0; b < B_; b++) acc[b] = make_float4(0.f, 0.f, 0.f, 0.f);
#pragma unroll
    for (int n = 0; n < NEXP; n++) {
        float4 w = W4[n * stride4 + idx];
#pragma unroll
        for (int b = 0; b < B_; b++) {
            float s = sp[b * NEXP + n];
            acc[b].x += s * w.x; acc[b].y += s * w.y;
            acc[b].z += s * w.z; acc[b].w += s * w.w;
        }
    }
#pragma unroll
    for (int b = 0; b < B_; b++) {
        union { __nv_bfloat16 h[4]; uint2 u; } hi, lo;
        float f[4] = {acc[b].x, acc[b].y, acc[b].z, acc[b].w};
#pragma unroll
        for (int i = 0; i < 4; i++) {
            __nv_bfloat16 h = __float2bfloat16(f[i]);
            hi.h[i] = h;
            lo.h[i] = __float2bfloat16(f[i] - __bfloat162float(h));
        }
        reinterpret_cast<uint2*>(g_Whi)[b * stride4 + idx] = hi.u;
        reinterpret_cast<uint2*>(g_Wlo)[b * stride4 + idx] = lo.u;
    }
}

// ---------------- Kernel: mix bias ----------------
__global__ void mix_b_kernel(const float* __restrict__ p, const float* __restrict__ bias) {
    int idx = blockIdx.x * blockDim.x + threadIdx.x;
    if (idx >= B_ * DOUT_) return;
    int b = idx >> 10;
    int i = idx & 1023;
    float s = 0.f;
#pragma unroll
    for (int n = 0; n < NEXP; n++) s += p[b * NEXP + n] * bias[n * DOUT_ + i];
    g_mb[idx] = s;
}

// ---------------- mma.sync GEMM ----------------
// C[b][m][n] = sum_k X[b][m][k] * Wm[b][n][k] + mb[b][n]  (bf16 3-term split)
#define BM 128
#define BN 128
#define BKT 64
#define NT (DIN_ / BKT)       // 16

#define STAGE_BYTES 65536
#define OFF_AHI 0
#define OFF_ALO 16384
#define OFF_WHI 32768
#define OFF_WLO 49152
#define SM_BIAS (2 * STAGE_BYTES)
#define SMEM_TOTAL (2 * STAGE_BYTES + 512)

// load one k-tile (4 matrices of [128 rows x 64 bf16], swizzled 128B rows)
__device__ __forceinline__ void load_kt(uint32_t stage_base, int b, int m0, int n0,
                                        int kt, int tid) {
    const __nv_bfloat16* xa_hi = g_Xhi + ((size_t)b * S_ + m0) * DIN_ + kt * BKT;
    const __nv_bfloat16* xa_lo = g_Xlo + ((size_t)b * S_ + m0) * DIN_ + kt * BKT;
    const __nv_bfloat16* wb_hi = g_Whi + ((size_t)b * DOUT_ + n0) * DIN_ + kt * BKT;
    const __nv_bfloat16* wb_lo = g_Wlo + ((size_t)b * DOUT_ + n0) * DIN_ + kt * BKT;

#pragma unroll
    for (int i = 0; i < 4; i++) {
        int c = tid + 256 * i;          // 0..1023
        int row = c >> 3, c16 = c & 7;
        uint32_t so = swz(row * 128 + c16 * 16);
        size_t go = (size_t)row * DIN_ + c16 * 8;
        cpa16(stage_base + OFF_AHI + so, xa_hi + go);
        cpa16(stage_base + OFF_ALO + so, xa_lo + go);
        cpa16(stage_base + OFF_WHI + so, wb_hi + go);
        cpa16(stage_base + OFF_WLO + so, wb_lo + go);
    }
    cpa_commit();
}

__global__ __launch_bounds__(256, 1) void gemm_kernel(float* __restrict__ Out) {
    extern __shared__ char smem[];
    const uint32_t sb = smem_u32(smem);
    const int tid = threadIdx.x;
    const int wid = tid >> 5;
    const int lane = tid & 31;

    const int b  = blockIdx.z;
    const int m0 = blockIdx.y * BM;
    const int n0 = blockIdx.x * BN;

    const int wm = (wid >> 1) * 32;   // warp m offset (4 warps in m)
    const int wn = (wid & 1) * 64;    // warp n offset (2 warps in n)

    // bias tile -> smem
    if (tid < 128) {
        reinterpret_cast<float*>(smem + SM_BIAS)[tid] = g_mb[b * DOUT_ + n0 + tid];
    }

    float acc[2][8][4];
#pragma unroll
    for (int mi = 0; mi < 2; mi++)
#pragma unroll
        for (int nb = 0; nb < 8; nb++)
#pragma unroll
            for (int j = 0; j < 4; j++) acc[mi][nb][j] = 0.f;

    // prologue: 2 stages in flight
    load_kt(sb, b, m0, n0, 0, tid);
    load_kt(sb + STAGE_BYTES, b, m0, n0, 1, tid);

    // per-lane ldmatrix address components
    const int a_row  = lane & 15;           // row within 16-row block
    const int a_col8 = (lane >> 4) * 8;     // k-halfblock
    const int b_nhalf = lane >> 4;          // which n8 of the pair
    const int b_khalf = (lane >> 3) & 1;
    const int b_row   = lane & 7;

    for (int kt = 0; kt < NT; kt++) {
        const uint32_t stage = sb + (uint32_t)(kt & 1) * STAGE_BYTES;

        if (kt < NT - 1) cpa_wait1(); else cpa_wait0();
        __syncthreads();

#pragma unroll
        for (int ks = 0; ks < 4; ks++) {
            const int k0 = ks * 16;

            uint32_t ahi[2][4], alo[2][4], whi[4][4], wlo[4][4];

            // A addresses
#pragma unroll
            for (int mi = 0; mi < 2; mi++) {
                uint32_t off = swz((uint32_t)(wm + mi * 16 + a_row) * 128 +
                                   (uint32_t)(k0 + a_col8) * 2);
                ldsm_x4(ahi[mi], stage + OFF_AHI + off);
                ldsm_x4(alo[mi], stage + OFF_ALO + off);
            }
            // B addresses: pair p covers n-blocks 2p, 2p+1
#pragma unroll
            for (int p = 0; p < 4; p++) {
                int nrow = wn + (p * 2 + b_nhalf) * 8 + b_row;
                uint32_t off = swz((uint32_t)nrow * 128 +
                                   (uint32_t)(k0 + b_khalf * 8) * 2);
                ldsm_x4(whi[p], stage + OFF_WHI + off);
                ldsm_x4(wlo[p], stage + OFF_WLO + off);
            }

            // term 0: Ahi * Whi
#pragma unroll
            for (int mi = 0; mi < 2; mi++)
#pragma unroll
                for (int nb = 0; nb < 8; nb++)
                    mma16816(acc[mi][nb], ahi[mi], whi[nb >> 1][(nb & 1) * 2],
                             whi[nb >> 1][(nb & 1) * 2 + 1]);
            // term 1: Ahi * Wlo
#pragma unroll
            for (int mi = 0; mi < 2; mi++)
#pragma unroll
                for (int nb = 0; nb < 8; nb++)
                    mma16816(acc[mi][nb], ahi[mi], wlo[nb >> 1][(nb & 1) * 2],
                             wlo[nb >> 1][(nb & 1) * 2 + 1]);
            // term 2: Alo * Whi
#pragma unroll
            for (int mi = 0; mi < 2; mi++)
#pragma unroll
                for (int nb = 0; nb < 8; nb++)
                    mma16816(acc[mi][nb], alo[mi], whi[nb >> 1][(nb & 1) * 2],
                             whi[nb >> 1][(nb & 1) * 2 + 1]);
        }

        __syncthreads();
        if (kt + 2 < NT) load_kt(stage, b, m0, n0, kt + 2, tid);
    }

    // epilogue: acc + bias -> Out
    const float* sBias = reinterpret_cast<const float*>(smem + SM_BIAS);
    const int c_row = lane >> 2;
    const int c_col = 2 * (lane & 3);
#pragma unroll
    for (int mi = 0; mi < 2; mi++) {
        int row0 = m0 + wm + mi * 16 + c_row;
        float* o0 = Out + ((size_t)b * S_ + row0) * DOUT_ + n0;
        float* o1 = o0 + 8 * DOUT_;
#pragma unroll
        for (int nb = 0; nb < 8; nb++) {
            int col = wn + nb * 8 + c_col;
            float bx = sBias[col], by = sBias[col + 1];
            float2 v0 = make_float2(acc[mi][nb][0] + bx, acc[mi][nb][1] + by);
            float2 v1 = make_float2(acc[mi][nb][2] + bx, acc[mi][nb][3] + by);
            *reinterpret_cast<float2*>(o0 + col) = v0;
            *reinterpret_cast<float2*>(o1 + col) = v1;
        }
    }
}

// ---------------- launch ----------------
extern "C" void kernel_launch(void* const* d_in, const int* in_sizes, int n_in,
                              void* d_out, int out_size) {
    const float* x    = (const float*)d_in[0];   // [B, S, DIN]
    const float* p    = (const float*)d_in[1];   // [B, N]
    const float* W    = (const float*)d_in[2];   // [N, DOUT, DIN]
    const float* bias = (const float*)d_in[3];   // [N, DOUT]
    float* out = (float*)d_out;                  // [B, S, DOUT]

    cudaFuncSetAttribute(gemm_kernel, cudaFuncAttributeMaxDynamicSharedMemorySize,
                         SMEM_TOTAL);

    {
        int total4 = B_ * S_ * DIN_ / 4;
        conv_x_kernel<<<(total4 + 255) / 256, 256>>>(x);
    }
    {
        int total4 = DOUT_ * DIN_ / 4;
        mix_w_kernel<<<(total4 + 255) / 256, 256>>>(p, W);
    }
    {
        int total = B_ * DOUT_;
        mix_b_kernel<<<(total + 255) / 256, 256>>>(p, bias);
    }
    {
        dim3 grid(DOUT_ / BN, S_ / BM, B_);      // (8, 16, 8) = 1024 CTAs
        gemm_kernel<<<grid, 256, SMEM_TOTAL>>>(out);
    }
}

// round 4
// speedup vs baseline: 3.9519x; 1.2498x over previous
#include <cuda_runtime.h>
#include <cuda_fp16.h>
#include <cstdint>

#define B_    8
#define S_    2048
#define NEXP  16
#define DIN_  1024
#define DOUT_ 1024

// ---------------- scratch (__device__ globals; no cudaMalloc allowed) ----------------
__device__ __align__(1024) __half g_Xhi[B_ * S_ * DIN_];
__device__ __align__(1024) __half g_Xlo[B_ * S_ * DIN_];
__device__ __align__(1024) __half g_Whi[B_ * DOUT_ * DIN_];
__device__ float g_mb[B_ * DOUT_];

// ---------------- PTX helpers (target-generic, sm_80+) ----------------
__device__ __forceinline__ uint32_t smem_u32(const void* p) {
    uint32_t a;
    asm("{ .reg .u64 t; cvta.to.shared.u64 t, %1; cvt.u32.u64 %0, t; }" : "=r"(a) : "l"(p));
    return a;
}
__device__ __forceinline__ void cpa16(uint32_t s, const void* g) {
    asm volatile("cp.async.cg.shared.global [%0], [%1], 16;" :: "r"(s), "l"(g));
}
__device__ __forceinline__ void cpa_commit() { asm volatile("cp.async.commit_group;" ::: "memory"); }
__device__ __forceinline__ void cpa_wait1()  { asm volatile("cp.async.wait_group 1;" ::: "memory"); }
__device__ __forceinline__ void cpa_wait0()  { asm volatile("cp.async.wait_group 0;" ::: "memory"); }

__device__ __forceinline__ void ldsm_x4(uint32_t (&r)[4], uint32_t addr) {
    asm volatile("ldmatrix.sync.aligned.m8n8.x4.shared.b16 {%0,%1,%2,%3}, [%4];"
                 : "=r"(r[0]), "=r"(r[1]), "=r"(r[2]), "=r"(r[3]) : "r"(addr));
}
__device__ __forceinline__ void mma16816(float (&d)[4], const uint32_t (&a)[4],
                                         uint32_t b0, uint32_t b1) {
    asm volatile(
        "mma.sync.aligned.m16n8k16.row.col.f32.f16.f16.f32 "
        "{%0,%1,%2,%3}, {%4,%5,%6,%7}, {%8,%9}, {%0,%1,%2,%3};"
        : "+f"(d[0]), "+f"(d[1]), "+f"(d[2]), "+f"(d[3])
        : "r"(a[0]), "r"(a[1]), "r"(a[2]), "r"(a[3]), "r"(b0), "r"(b1));
}

static __device__ __forceinline__ uint32_t swz(uint32_t off) {
    return off ^ ((off >> 3) & 0x70);
}

// ---------------- Kernel: X -> hi/lo fp16 ----------------
__global__ void conv_x_kernel(const float* __restrict__ X) {
    int idx = blockIdx.x * blockDim.x + threadIdx.x;
    const int total4 = B_ * S_ * DIN_ / 4;
    if (idx >= total4) return;
    float4 v = reinterpret_cast<const float4*>(X)[idx];
    union { __half h[4]; uint2 u; } hi, lo;
    float f[4] = {v.x, v.y, v.z, v.w};
#pragma unroll
    for (int i = 0; i < 4; i++) {
        __half h = __float2half_rn(f[i]);
        hi.h[i] = h;
        lo.h[i] = __float2half_rn(f[i] - __half2float(h));
    }
    reinterpret_cast<uint2*>(g_Xhi)[idx] = hi.u;
    reinterpret_cast<uint2*>(g_Xlo)[idx] = lo.u;
}

// ---------------- Kernel: mix weights -> fp16 ----------------
__global__ void mix_w_kernel(const float* __restrict__ p, const float* __restrict__ W) {
    __shared__ float sp[B_ * NEXP];
    if (threadIdx.x < B_ * NEXP) sp[threadIdx.x] = p[threadIdx.x];
    __syncthreads();

    int idx = blockIdx.x * blockDim.x + threadIdx.x;
    const int stride4 = DOUT_ * DIN_ / 4;
    if (idx >= stride4) return;

    const float4* W4 = reinterpret_cast<const float4*>(W);
    float4 acc[B_];
#pragma unroll
    for (int b = 0; b < B_; b++) acc[b] = make_float4(0.f, 0.f, 0.f, 0.f);
#pragma unroll
    for (int n = 0; n < NEXP; n++) {
        float4 w = W4[n * stride4 + idx];
#pragma unroll
        for (int b = 0; b < B_; b++) {
            float s = sp[b * NEXP + n];
            acc[b].x += s * w.x; acc[b].y += s * w.y;
            acc[b].z += s * w.z; acc[b].w += s * w.w;
        }
    }
#pragma unroll
    for (int b = 0; b < B_; b++) {
        union { __half h[4]; uint2 u; } hi;
        hi.h[0] = __float2half_rn(acc[b].x);
        hi.h[1] = __float2half_rn(acc[b].y);
        hi.h[2] = __float2half_rn(acc[b].z);
        hi.h[3] = __float2half_rn(acc[b].w);
        reinterpret_cast<uint2*>(g_Whi)[b * stride4 + idx] = hi.u;
    }
}

// ---------------- Kernel: mix bias ----------------
__global__ void mix_b_kernel(const float* __restrict__ p, const float* __restrict__ bias) {
    int idx = blockIdx.x * blockDim.x + threadIdx.x;
    if (idx >= B_ * DOUT_) return;
    int b = idx >> 10;
    int i = idx & 1023;
    float s = 0.f;
#pragma unroll
    for (int n = 0; n < NEXP; n++) s += p[b * NEXP + n] * bias[n * DOUT_ + i];
    g_mb[idx] = s;
}

// ---------------- mma.sync GEMM ----------------
// C[b][m][n] = (Xhi + Xlo)[b][m][:] . Whi[b][n][:] + mb[b][n]
#define BM 128
#define BN 128
#define BKT 64
#define NT (DIN_ / BKT)       // 16
#define NSTAGE 3

#define STAGE_BYTES 49152
#define OFF_AHI 0
#define OFF_ALO 16384
#define OFF_WHI 32768
#define SM_BIAS (NSTAGE * STAGE_BYTES)
#define SMEM_TOTAL (NSTAGE * STAGE_BYTES + 512)

// load one k-tile (3 matrices of [128 rows x 64 fp16], swizzled 128B rows)
__device__ __forceinline__ void load_kt(uint32_t stage_base, int b, int m0, int n0,
                                        int kt, int tid) {
    const __half* xa_hi = g_Xhi + ((size_t)b * S_ + m0) * DIN_ + kt * BKT;
    const __half* xa_lo = g_Xlo + ((size_t)b * S_ + m0) * DIN_ + kt * BKT;
    const __half* wb_hi = g_Whi + ((size_t)b * DOUT_ + n0) * DIN_ + kt * BKT;

#pragma unroll
    for (int i = 0; i < 4; i++) {
        int c = tid + 256 * i;          // 0..1023
        int row = c >> 3, c16 = c & 7;
        uint32_t so = swz(row * 128 + c16 * 16);
        size_t go = (size_t)row * DIN_ + c16 * 8;
        cpa16(stage_base + OFF_AHI + so, xa_hi + go);
        cpa16(stage_base + OFF_ALO + so, xa_lo + go);
        cpa16(stage_base + OFF_WHI + so, wb_hi + go);
    }
    cpa_commit();
}

__global__ __launch_bounds__(256, 1) void gemm_kernel(float* __restrict__ Out) {
    extern __shared__ char smem[];
    const uint32_t sb = smem_u32(smem);
    const int tid = threadIdx.x;
    const int wid = tid >> 5;
    const int lane = tid & 31;

    const int b  = blockIdx.z;
    const int m0 = blockIdx.y * BM;
    const int n0 = blockIdx.x * BN;

    const int wm = (wid >> 1) * 32;   // warp m offset (4 warps in m)
    const int wn = (wid & 1) * 64;    // warp n offset (2 warps in n)

    if (tid < 128) {
        reinterpret_cast<float*>(smem + SM_BIAS)[tid] = g_mb[b * DOUT_ + n0 + tid];
    }

    float acc[2][8][4];
#pragma unroll
    for (int mi = 0; mi < 2; mi++)
#pragma unroll
        for (int nb = 0; nb < 8; nb++)
#pragma unroll
            for (int j = 0; j < 4; j++) acc[mi][nb][j] = 0.f;

    // prologue: 2 stages in flight
    load_kt(sb, b, m0, n0, 0, tid);
    load_kt(sb + STAGE_BYTES, b, m0, n0, 1, tid);

    const int a_row  = lane & 15;
    const int a_col8 = (lane >> 4) * 8;
    const int b_nhalf = lane >> 4;
    const int b_khalf = (lane >> 3) & 1;
    const int b_row   = lane & 7;

    uint32_t stage_off[NSTAGE] = {0, STAGE_BYTES, 2 * STAGE_BYTES};

    for (int kt = 0; kt < NT; kt++) {
        const uint32_t stage = sb + stage_off[kt % NSTAGE];

        if (kt < NT - 1) cpa_wait1(); else cpa_wait0();
        __syncthreads();

        // issue next-next tile load first (stage consumed at kt-1; sync above protects it)
        if (kt + 2 < NT) {
            load_kt(sb + stage_off[(kt + 2) % NSTAGE], b, m0, n0, kt + 2, tid);
        }

#pragma unroll
        for (int ks = 0; ks < 4; ks++) {
            const int k0 = ks * 16;

            uint32_t ahi[2][4], alo[2][4], whi[4][4];

#pragma unroll
            for (int mi = 0; mi < 2; mi++) {
                uint32_t off = swz((uint32_t)(wm + mi * 16 + a_row) * 128 +
                                   (uint32_t)(k0 + a_col8) * 2);
                ldsm_x4(ahi[mi], stage + OFF_AHI + off);
                ldsm_x4(alo[mi], stage + OFF_ALO + off);
            }
#pragma unroll
            for (int p = 0; p < 4; p++) {
                int nrow = wn + (p * 2 + b_nhalf) * 8 + b_row;
                uint32_t off = swz((uint32_t)nrow * 128 +
                                   (uint32_t)(k0 + b_khalf * 8) * 2);
                ldsm_x4(whi[p], stage + OFF_WHI + off);
            }

            // term 0: Ahi * Whi
#pragma unroll
            for (int mi = 0; mi < 2; mi++)
#pragma unroll
                for (int nb = 0; nb < 8; nb++)
                    mma16816(acc[mi][nb], ahi[mi], whi[nb >> 1][(nb & 1) * 2],
                             whi[nb >> 1][(nb & 1) * 2 + 1]);
            // term 1: Alo * Whi
#pragma unroll
            for (int mi = 0; mi < 2; mi++)
#pragma unroll
                for (int nb = 0; nb < 8; nb++)
                    mma16816(acc[mi][nb], alo[mi], whi[nb >> 1][(nb & 1) * 2],
                             whi[nb >> 1][(nb & 1) * 2 + 1]);
        }
        __syncthreads();
    }

    // epilogue: acc + bias -> Out
    const float* sBias = reinterpret_cast<const float*>(smem + SM_BIAS);
    const int c_row = lane >> 2;
    const int c_col = 2 * (lane & 3);
#pragma unroll
    for (int mi = 0; mi < 2; mi++) {
        int row0 = m0 + wm + mi * 16 + c_row;
        float* o0 = Out + ((size_t)b * S_ + row0) * DOUT_ + n0;
        float* o1 = o0 + 8 * DOUT_;
#pragma unroll
        for (int nb = 0; nb < 8; nb++) {
            int col = wn + nb * 8 + c_col;
            float bx = sBias[col], by = sBias[col + 1];
            float2 v0 = make_float2(acc[mi][nb][0] + bx, acc[mi][nb][1] + by);
            float2 v1 = make_float2(acc[mi][nb][2] + bx, acc[mi][nb][3] + by);
            *reinterpret_cast<float2*>(o0 + col) = v0;
            *reinterpret_cast<float2*>(o1 + col) = v1;
        }
    }
}

// ---------------- launch ----------------
extern "C" void kernel_launch(void* const* d_in, const int* in_sizes, int n_in,
                              void* d_out, int out_size) {
    const float* x    = (const float*)d_in[0];   // [B, S, DIN]
    const float* p    = (const float*)d_in[1];   // [B, N]
    const float* W    = (const float*)d_in[2];   // [N, DOUT, DIN]
    const float* bias = (const float*)d_in[3];   // [N, DOUT]
    float* out = (float*)d_out;                  // [B, S, DOUT]

    cudaFuncSetAttribute(gemm_kernel, cudaFuncAttributeMaxDynamicSharedMemorySize,
                         SMEM_TOTAL);

    {
        int total4 = B_ * S_ * DIN_ / 4;
        conv_x_kernel<<<(total4 + 255) / 256, 256>>>(x);
    }
    {
        int total4 = DOUT_ * DIN_ / 4;
        mix_w_kernel<<<(total4 + 255) / 256, 256>>>(p, W);
    }
    {
        int total = B_ * DOUT_;
        mix_b_kernel<<<(total + 255) / 256, 256>>>(p, bias);
    }
    {
        dim3 grid(DOUT_ / BN, S_ / BM, B_);      // (8, 16, 8) = 1024 CTAs
        gemm_kernel<<<grid, 256, SMEM_TOTAL>>>(out);
    }
}

// round 5
// speedup vs baseline: 6.1228x; 1.5493x over previous
#include <cuda_runtime.h>
#include <cuda_fp16.h>
#include <cstdint>

#define B_    8
#define S_    2048
#define NEXP  16
#define DIN_  1024
#define DOUT_ 1024

// ---------------- scratch ----------------
__device__ __align__(1024) __half g_Xhi[B_ * S_ * DIN_];
__device__ __align__(1024) __half g_Whi[B_ * DOUT_ * DIN_];
__device__ float g_mb[B_ * DOUT_];

// ---------------- PTX helpers (target-generic, sm_80+) ----------------
__device__ __forceinline__ uint32_t smem_u32(const void* p) {
    uint32_t a;
    asm("{ .reg .u64 t; cvta.to.shared.u64 t, %1; cvt.u32.u64 %0, t; }" : "=r"(a) : "l"(p));
    return a;
}
__device__ __forceinline__ void cpa16(uint32_t s, const void* g) {
    asm volatile("cp.async.cg.shared.global [%0], [%1], 16;" :: "r"(s), "l"(g));
}
__device__ __forceinline__ void cpa_commit() { asm volatile("cp.async.commit_group;" ::: "memory"); }
__device__ __forceinline__ void cpa_wait1()  { asm volatile("cp.async.wait_group 1;" ::: "memory"); }
__device__ __forceinline__ void cpa_wait0()  { asm volatile("cp.async.wait_group 0;" ::: "memory"); }

__device__ __forceinline__ void ldsm_x4(uint32_t (&r)[4], uint32_t addr) {
    asm volatile("ldmatrix.sync.aligned.m8n8.x4.shared.b16 {%0,%1,%2,%3}, [%4];"
                 : "=r"(r[0]), "=r"(r[1]), "=r"(r[2]), "=r"(r[3]) : "r"(addr));
}
__device__ __forceinline__ void mma16816(float (&d)[4], const uint32_t (&a)[4],
                                         uint32_t b0, uint32_t b1) {
    asm volatile(
        "mma.sync.aligned.m16n8k16.row.col.f32.f16.f16.f32 "
        "{%0,%1,%2,%3}, {%4,%5,%6,%7}, {%8,%9}, {%0,%1,%2,%3};"
        : "+f"(d[0]), "+f"(d[1]), "+f"(d[2]), "+f"(d[3])
        : "r"(a[0]), "r"(a[1]), "r"(a[2]), "r"(a[3]), "r"(b0), "r"(b1));
}

static __device__ __forceinline__ uint32_t swz(uint32_t off) {
    return off ^ ((off >> 3) & 0x70);
}

// ---------------- merged prep kernel ----------------
// blocks [0, NCONV)               : X -> fp16
// blocks [NCONV, NCONV+NMIXW)     : mixed W -> fp16
// blocks [NCONV+NMIXW, +NMIXB)    : mixed bias
#define NCONV (B_ * S_ * DIN_ / 4 / 256)       // 16384
#define NMIXW (DOUT_ * DIN_ / 4 / 256)         // 1024
#define NMIXB (B_ * DOUT_ / 256)               // 32

__global__ void prep_kernel(const float* __restrict__ X, const float* __restrict__ p,
                            const float* __restrict__ W, const float* __restrict__ bias) {
    const int bid = blockIdx.x;
    if (bid < NCONV) {
        int idx = bid * 256 + threadIdx.x;
        float4 v = reinterpret_cast<const float4*>(X)[idx];
        union { __half h[4]; uint2 u; } hi;
        hi.h[0] = __float2half_rn(v.x);
        hi.h[1] = __float2half_rn(v.y);
        hi.h[2] = __float2half_rn(v.z);
        hi.h[3] = __float2half_rn(v.w);
        reinterpret_cast<uint2*>(g_Xhi)[idx] = hi.u;
    } else if (bid < NCONV + NMIXW) {
        __shared__ float sp[B_ * NEXP];
        if (threadIdx.x < B_ * NEXP) sp[threadIdx.x] = p[threadIdx.x];
        __syncthreads();

        int idx = (bid - NCONV) * 256 + threadIdx.x;
        const int stride4 = DOUT_ * DIN_ / 4;
        const float4* W4 = reinterpret_cast<const float4*>(W);
        float4 acc[B_];
#pragma unroll
        for (int b = 0; b < B_; b++) acc[b] = make_float4(0.f, 0.f, 0.f, 0.f);
#pragma unroll
        for (int n = 0; n < NEXP; n++) {
            float4 w = W4[n * stride4 + idx];
#pragma unroll
            for (int b = 0; b < B_; b++) {
                float s = sp[b * NEXP + n];
                acc[b].x += s * w.x; acc[b].y += s * w.y;
                acc[b].z += s * w.z; acc[b].w += s * w.w;
            }
        }
#pragma unroll
        for (int b = 0; b < B_; b++) {
            union { __half h[4]; uint2 u; } hi;
            hi.h[0] = __float2half_rn(acc[b].x);
            hi.h[1] = __float2half_rn(acc[b].y);
            hi.h[2] = __float2half_rn(acc[b].z);
            hi.h[3] = __float2half_rn(acc[b].w);
            reinterpret_cast<uint2*>(g_Whi)[b * stride4 + idx] = hi.u;
        }
    } else {
        int idx = (bid - NCONV - NMIXW) * 256 + threadIdx.x;
        int b = idx >> 10;
        int i = idx & 1023;
        float s = 0.f;
#pragma unroll
        for (int n = 0; n < NEXP; n++) s += p[b * NEXP + n] * bias[n * DOUT_ + i];
        g_mb[idx] = s;
    }
}

// ---------------- mma.sync GEMM (single fp16 term) ----------------
#define BM 128
#define BN 128
#define BKT 64
#define NT (DIN_ / BKT)       // 16
#define NSTAGE 3

#define STAGE_BYTES 32768
#define OFF_A 0
#define OFF_W 16384
#define SM_BIAS (NSTAGE * STAGE_BYTES)
#define SMEM_TOTAL (NSTAGE * STAGE_BYTES + 512)   // 98816

__device__ __forceinline__ void load_kt(uint32_t stage_base, int b, int m0, int n0,
                                        int kt, int tid) {
    const __half* xa = g_Xhi + ((size_t)b * S_ + m0) * DIN_ + kt * BKT;
    const __half* wb = g_Whi + ((size_t)b * DOUT_ + n0) * DIN_ + kt * BKT;

#pragma unroll
    for (int i = 0; i < 4; i++) {
        int c = tid + 256 * i;          // 0..1023
        int row = c >> 3, c16 = c & 7;
        uint32_t so = swz(row * 128 + c16 * 16);
        size_t go = (size_t)row * DIN_ + c16 * 8;
        cpa16(stage_base + OFF_A + so, xa + go);
        cpa16(stage_base + OFF_W + so, wb + go);
    }
    cpa_commit();
}

__global__ __launch_bounds__(256, 2) void gemm_kernel(float* __restrict__ Out) {
    extern __shared__ char smem[];
    const uint32_t sb = smem_u32(smem);
    const int tid = threadIdx.x;
    const int wid = tid >> 5;
    const int lane = tid & 31;

    const int b  = blockIdx.z;
    const int m0 = blockIdx.y * BM;
    const int n0 = blockIdx.x * BN;

    const int wm = (wid >> 1) * 32;   // 4 warps in m
    const int wn = (wid & 1) * 64;    // 2 warps in n

    if (tid < 128) {
        reinterpret_cast<float*>(smem + SM_BIAS)[tid] = g_mb[b * DOUT_ + n0 + tid];
    }

    float acc[2][8][4];
#pragma unroll
    for (int mi = 0; mi < 2; mi++)
#pragma unroll
        for (int nb = 0; nb < 8; nb++)
#pragma unroll
            for (int j = 0; j < 4; j++) acc[mi][nb][j] = 0.f;

    load_kt(sb, b, m0, n0, 0, tid);
    load_kt(sb + STAGE_BYTES, b, m0, n0, 1, tid);

    const int a_row  = lane & 15;
    const int a_col8 = (lane >> 4) * 8;
    const int b_nhalf = lane >> 4;
    const int b_khalf = (lane >> 3) & 1;
    const int b_row   = lane & 7;

    uint32_t stage_off[NSTAGE] = {0, STAGE_BYTES, 2 * STAGE_BYTES};

    for (int kt = 0; kt < NT; kt++) {
        const uint32_t stage = sb + stage_off[kt % NSTAGE];

        if (kt < NT - 1) cpa_wait1(); else cpa_wait0();
        __syncthreads();

        if (kt + 2 < NT) {
            load_kt(sb + stage_off[(kt + 2) % NSTAGE], b, m0, n0, kt + 2, tid);
        }

#pragma unroll
        for (int ks = 0; ks < 4; ks++) {
            const int k0 = ks * 16;

            uint32_t ahi[2][4], whi[4][4];

#pragma unroll
            for (int mi = 0; mi < 2; mi++) {
                uint32_t off = swz((uint32_t)(wm + mi * 16 + a_row) * 128 +
                                   (uint32_t)(k0 + a_col8) * 2);
                ldsm_x4(ahi[mi], stage + OFF_A + off);
            }
#pragma unroll
            for (int p = 0; p < 4; p++) {
                int nrow = wn + (p * 2 + b_nhalf) * 8 + b_row;
                uint32_t off = swz((uint32_t)nrow * 128 +
                                   (uint32_t)(k0 + b_khalf * 8) * 2);
                ldsm_x4(whi[p], stage + OFF_W + off);
            }

#pragma unroll
            for (int mi = 0; mi < 2; mi++)
#pragma unroll
                for (int nb = 0; nb < 8; nb++)
                    mma16816(acc[mi][nb], ahi[mi], whi[nb >> 1][(nb & 1) * 2],
                             whi[nb >> 1][(nb & 1) * 2 + 1]);
        }
        __syncthreads();
    }

    const float* sBias = reinterpret_cast<const float*>(smem + SM_BIAS);
    const int c_row = lane >> 2;
    const int c_col = 2 * (lane & 3);
#pragma unroll
    for (int mi = 0; mi < 2; mi++) {
        int row0 = m0 + wm + mi * 16 + c_row;
        float* o0 = Out + ((size_t)b * S_ + row0) * DOUT_ + n0;
        float* o1 = o0 + 8 * DOUT_;
#pragma unroll
        for (int nb = 0; nb < 8; nb++) {
            int col = wn + nb * 8 + c_col;
            float bx = sBias[col], by = sBias[col + 1];
            float2 v0 = make_float2(acc[mi][nb][0] + bx, acc[mi][nb][1] + by);
            float2 v1 = make_float2(acc[mi][nb][2] + bx, acc[mi][nb][3] + by);
            *reinterpret_cast<float2*>(o0 + col) = v0;
            *reinterpret_cast<float2*>(o1 + col) = v1;
        }
    }
}

// ---------------- launch ----------------
extern "C" void kernel_launch(void* const* d_in, const int* in_sizes, int n_in,
                              void* d_out, int out_size) {
    const float* x    = (const float*)d_in[0];   // [B, S, DIN]
    const float* p    = (const float*)d_in[1];   // [B, N]
    const float* W    = (const float*)d_in[2];   // [N, DOUT, DIN]
    const float* bias = (const float*)d_in[3];   // [N, DOUT]
    float* out = (float*)d_out;                  // [B, S, DOUT]

    cudaFuncSetAttribute(gemm_kernel, cudaFuncAttributeMaxDynamicSharedMemorySize,
                         SMEM_TOTAL);

    prep_kernel<<<NCONV + NMIXW + NMIXB, 256>>>(x, p, W, bias);

    dim3 grid(DOUT_ / BN, S_ / BM, B_);          // (8, 16, 8) = 1024 CTAs
    gemm_kernel<<<grid, 256, SMEM_TOTAL>>>(out);
}

// round 6
// speedup vs baseline: 6.2657x; 1.0233x over previous
#include <cuda_runtime.h>
#include <cuda_fp16.h>
#include <cstdint>

#define B_    8
#define S_    2048
#define NEXP  16
#define DIN_  1024
#define DOUT_ 1024

// ---------------- scratch ----------------
__device__ __align__(1024) __half g_Xhi[B_ * S_ * DIN_];
__device__ __align__(1024) __half g_Whi[B_ * DOUT_ * DIN_];
__device__ float g_mb[B_ * DOUT_];

// ---------------- PTX helpers (target-generic, sm_80+) ----------------
__device__ __forceinline__ uint32_t smem_u32(const void* p) {
    uint32_t a;
    asm("{ .reg .u64 t; cvta.to.shared.u64 t, %1; cvt.u32.u64 %0, t; }" : "=r"(a) : "l"(p));
    return a;
}
__device__ __forceinline__ void cpa16(uint32_t s, const void* g) {
    asm volatile("cp.async.cg.shared.global [%0], [%1], 16;" :: "r"(s), "l"(g));
}
__device__ __forceinline__ void cpa_commit() { asm volatile("cp.async.commit_group;" ::: "memory"); }
__device__ __forceinline__ void cpa_wait1()  { asm volatile("cp.async.wait_group 1;" ::: "memory"); }
__device__ __forceinline__ void cpa_wait0()  { asm volatile("cp.async.wait_group 0;" ::: "memory"); }

__device__ __forceinline__ void ldsm_x4(uint32_t (&r)[4], uint32_t addr) {
    asm volatile("ldmatrix.sync.aligned.m8n8.x4.shared.b16 {%0,%1,%2,%3}, [%4];"
                 : "=r"(r[0]), "=r"(r[1]), "=r"(r[2]), "=r"(r[3]) : "r"(addr));
}
__device__ __forceinline__ void mma16816(float (&d)[4], const uint32_t (&a)[4],
                                         uint32_t b0, uint32_t b1) {
    asm volatile(
        "mma.sync.aligned.m16n8k16.row.col.f32.f16.f16.f32 "
        "{%0,%1,%2,%3}, {%4,%5,%6,%7}, {%8,%9}, {%0,%1,%2,%3};"
        : "+f"(d[0]), "+f"(d[1]), "+f"(d[2]), "+f"(d[3])
        : "r"(a[0]), "r"(a[1]), "r"(a[2]), "r"(a[3]), "r"(b0), "r"(b1));
}

static __device__ __forceinline__ uint32_t swz(uint32_t off) {
    return off ^ ((off >> 3) & 0x70);
}

// ---------------- merged prep kernel ----------------
// Heavy mix_w blocks FIRST (long pole), then bias, then light conv blocks.
#define NMIXW (DOUT_ * DIN_ / 4 / 256)         // 1024
#define NMIXB (B_ * DOUT_ / 256)               // 32
#define NCONV (B_ * S_ * DIN_ / 4 / 256)       // 16384

__global__ void prep_kernel(const float* __restrict__ X, const float* __restrict__ p,
                            const float* __restrict__ W, const float* __restrict__ bias) {
    const int bid = blockIdx.x;
    if (bid < NMIXW) {
        __shared__ float sp[B_ * NEXP];
        if (threadIdx.x < B_ * NEXP) sp[threadIdx.x] = p[threadIdx.x];
        __syncthreads();

        int idx = bid * 256 + threadIdx.x;
        const int stride4 = DOUT_ * DIN_ / 4;
        const float4* W4 = reinterpret_cast<const float4*>(W);
        float4 acc[B_];
#pragma unroll
        for (int b = 0; b < B_; b++) acc[b] = make_float4(0.f, 0.f, 0.f, 0.f);
#pragma unroll
        for (int n = 0; n < NEXP; n++) {
            float4 w = W4[n * stride4 + idx];
#pragma unroll
            for (int b = 0; b < B_; b++) {
                float s = sp[b * NEXP + n];
                acc[b].x += s * w.x; acc[b].y += s * w.y;
                acc[b].z += s * w.z; acc[b].w += s * w.w;
            }
        }
#pragma unroll
        for (int b = 0; b < B_; b++) {
            union { __half h[4]; uint2 u; } hi;
            hi.h[0] = __float2half_rn(acc[b].x);
            hi.h[1] = __float2half_rn(acc[b].y);
            hi.h[2] = __float2half_rn(acc[b].z);
            hi.h[3] = __float2half_rn(acc[b].w);
            reinterpret_cast<uint2*>(g_Whi)[b * stride4 + idx] = hi.u;
        }
    } else if (bid < NMIXW + NMIXB) {
        int idx = (bid - NMIXW) * 256 + threadIdx.x;
        int b = idx >> 10;
        int i = idx & 1023;
        float s = 0.f;
#pragma unroll
        for (int n = 0; n < NEXP; n++) s += p[b * NEXP + n] * bias[n * DOUT_ + i];
        g_mb[idx] = s;
    } else {
        int idx = (bid - NMIXW - NMIXB) * 256 + threadIdx.x;
        float4 v = reinterpret_cast<const float4*>(X)[idx];
        union { __half h[4]; uint2 u; } hi;
        hi.h[0] = __float2half_rn(v.x);
        hi.h[1] = __float2half_rn(v.y);
        hi.h[2] = __float2half_rn(v.z);
        hi.h[3] = __float2half_rn(v.w);
        reinterpret_cast<uint2*>(g_Xhi)[idx] = hi.u;
    }
}

// ---------------- mma.sync GEMM (single fp16 term) ----------------
#define BM 128
#define BN 128
#define BKT 64
#define NT (DIN_ / BKT)       // 16
#define NSTAGE 3

#define STAGE_BYTES 32768
#define OFF_A 0
#define OFF_W 16384
#define SM_BIAS (NSTAGE * STAGE_BYTES)
#define SMEM_TOTAL (NSTAGE * STAGE_BYTES + 512)   // 98816

__device__ __forceinline__ void load_kt(uint32_t stage_base, int b, int m0, int n0,
                                        int kt, int tid) {
    const __half* xa = g_Xhi + ((size_t)b * S_ + m0) * DIN_ + kt * BKT;
    const __half* wb = g_Whi + ((size_t)b * DOUT_ + n0) * DIN_ + kt * BKT;

#pragma unroll
    for (int i = 0; i < 4; i++) {
        int c = tid + 256 * i;          // 0..1023
        int row = c >> 3, c16 = c & 7;
        uint32_t so = swz(row * 128 + c16 * 16);
        size_t go = (size_t)row * DIN_ + c16 * 8;
        cpa16(stage_base + OFF_A + so, xa + go);
        cpa16(stage_base + OFF_W + so, wb + go);
    }
    cpa_commit();
}

__global__ __launch_bounds__(256, 2) void gemm_kernel(float* __restrict__ Out) {
    extern __shared__ char smem[];
    const uint32_t sb = smem_u32(smem);
    const int tid = threadIdx.x;
    const int wid = tid >> 5;
    const int lane = tid & 31;

    const int b  = blockIdx.z;
    const int m0 = blockIdx.y * BM;
    const int n0 = blockIdx.x * BN;

    const int wm = (wid >> 1) * 32;   // 4 warps in m
    const int wn = (wid & 1) * 64;    // 2 warps in n

    if (tid < 128) {
        reinterpret_cast<float*>(smem + SM_BIAS)[tid] = g_mb[b * DOUT_ + n0 + tid];
    }

    float acc[2][8][4];
#pragma unroll
    for (int mi = 0; mi < 2; mi++)
#pragma unroll
        for (int nb = 0; nb < 8; nb++)
#pragma unroll
            for (int j = 0; j < 4; j++) acc[mi][nb][j] = 0.f;

    load_kt(sb, b, m0, n0, 0, tid);
    load_kt(sb + STAGE_BYTES, b, m0, n0, 1, tid);

    const int a_row  = lane & 15;
    const int a_col8 = (lane >> 4) * 8;
    const int b_nhalf = lane >> 4;
    const int b_khalf = (lane >> 3) & 1;
    const int b_row   = lane & 7;

    uint32_t stage_off[NSTAGE] = {0, STAGE_BYTES, 2 * STAGE_BYTES};

    for (int kt = 0; kt < NT; kt++) {
        const uint32_t stage = sb + stage_off[kt % NSTAGE];

        if (kt < NT - 1) cpa_wait1(); else cpa_wait0();
        __syncthreads();
        // Single barrier per iteration: the load below targets stage (kt+2)%3
        // == (kt-1)%3, whose readers (iteration kt-1) all passed the barrier
        // above before this load is issued.
        if (kt + 2 < NT) {
            load_kt(sb + stage_off[(kt + 2) % NSTAGE], b, m0, n0, kt + 2, tid);
        }

#pragma unroll
        for (int ks = 0; ks < 4; ks++) {
            const int k0 = ks * 16;

            uint32_t ahi[2][4], whi[4][4];

#pragma unroll
            for (int mi = 0; mi < 2; mi++) {
                uint32_t off = swz((uint32_t)(wm + mi * 16 + a_row) * 128 +
                                   (uint32_t)(k0 + a_col8) * 2);
                ldsm_x4(ahi[mi], stage + OFF_A + off);
            }
#pragma unroll
            for (int p = 0; p < 4; p++) {
                int nrow = wn + (p * 2 + b_nhalf) * 8 + b_row;
                uint32_t off = swz((uint32_t)nrow * 128 +
                                   (uint32_t)(k0 + b_khalf * 8) * 2);
                ldsm_x4(whi[p], stage + OFF_W + off);
            }

#pragma unroll
            for (int mi = 0; mi < 2; mi++)
#pragma unroll
                for (int nb = 0; nb < 8; nb++)
                    mma16816(acc[mi][nb], ahi[mi], whi[nb >> 1][(nb & 1) * 2],
                             whi[nb >> 1][(nb & 1) * 2 + 1]);
        }
    }

    const float* sBias = reinterpret_cast<const float*>(smem + SM_BIAS);
    const int c_row = lane >> 2;
    const int c_col = 2 * (lane & 3);
#pragma unroll
    for (int mi = 0; mi < 2; mi++) {
        int row0 = m0 + wm + mi * 16 + c_row;
        float* o0 = Out + ((size_t)b * S_ + row0) * DOUT_ + n0;
        float* o1 = o0 + 8 * DOUT_;
#pragma unroll
        for (int nb = 0; nb < 8; nb++) {
            int col = wn + nb * 8 + c_col;
            float bx = sBias[col], by = sBias[col + 1];
            float2 v0 = make_float2(acc[mi][nb][0] + bx, acc[mi][nb][1] + by);
            float2 v1 = make_float2(acc[mi][nb][2] + bx, acc[mi][nb][3] + by);
            *reinterpret_cast<float2*>(o0 + col) = v0;
            *reinterpret_cast<float2*>(o1 + col) = v1;
        }
    }
}

// ---------------- launch ----------------
extern "C" void kernel_launch(void* const* d_in, const int* in_sizes, int n_in,
                              void* d_out, int out_size) {
    const float* x    = (const float*)d_in[0];   // [B, S, DIN]
    const float* p    = (const float*)d_in[1];   // [B, N]
    const float* W    = (const float*)d_in[2];   // [N, DOUT, DIN]
    const float* bias = (const float*)d_in[3];   // [N, DOUT]
    float* out = (float*)d_out;                  // [B, S, DOUT]

    cudaFuncSetAttribute(gemm_kernel, cudaFuncAttributeMaxDynamicSharedMemorySize,
                         SMEM_TOTAL);

    prep_kernel<<<NMIXW + NMIXB + NCONV, 256>>>(x, p, W, bias);

    dim3 grid(DOUT_ / BN, S_ / BM, B_);          // (8, 16, 8) = 1024 CTAs
    gemm_kernel<<<grid, 256, SMEM_TOTAL>>>(out);
}